// round 7
// baseline (speedup 1.0000x reference)
#include <cuda_runtime.h>
#include <cstdint>

#define NPTS   200000
#define KK     125
#define NTILES 1563

#define AROW   1096u           // ctx dup-A row stride (bytes)
#define ACH    272u            // chunk stride within row (bytes)
#define MLP_AS 260             // mlp X row stride (words)
#define RING_OFF 140288u       // 2 x 32768-byte B slots
#define SMEM_BYTES (140288 + 2*32768)

// ---------- PTX helpers ----------
__device__ __forceinline__ uint32_t smem_u32(const void* p){
    uint32_t a; asm("{ .reg .u64 t; cvta.to.shared.u64 t, %1; cvt.u32.u64 %0, t; }":"=r"(a):"l"(p)); return a;
}
#define CP_ASYNC16(dst,src) asm volatile("cp.async.cg.shared.global [%0], [%1], 16;"::"r"(dst),"l"(src):"memory")
#define CP_COMMIT() asm volatile("cp.async.commit_group;":::"memory")
#define CP_WAIT1()  asm volatile("cp.async.wait_group 1;":::"memory")
#define UNPK(lo,hi,p) asm volatile("mov.b64 {%0,%1}, %2;" : "=f"(lo),"=f"(hi) : "l"(p))

// ---------- device scratch ----------
__device__ int g_kflag[KK];
__device__ int g_act[KK];
__device__ int g_nact;
__device__ unsigned int g_done;

// ---------- prep: detect active taps (device-side) ----------
__global__ void prep_flag_compact(const float* __restrict__ Wm){
    int k = blockIdx.x, t = threadIdx.x, any = 0;
    const float* w = Wm + (size_t)k*32768;
    for (int i=t;i<32768;i+=256) any |= (w[i]!=0.f);
    any = __syncthreads_or(any);
    __shared__ unsigned int slast;
    if (t == 0){
        g_kflag[k] = any;
        __threadfence();
        slast = atomicAdd(&g_done, 1u);
    }
    __syncthreads();
    if (slast == KK-1 && t == 0){
        int c = 0;
        for (int kk=0; kk<KK; kk++){
            int fl = *((volatile int*)&g_kflag[kk]);
            if (fl) g_act[c++] = kk;
        }
        g_nact = c;
        g_done = 0;
        __threadfence();
    }
}

// ---------- ctx chunk: duplicated-A (no splat movs) ----------
__device__ __forceinline__ void chunk_dup(unsigned long long (&acc)[8][4], uint32_t abase, uint32_t bbase){
    #pragma unroll 4
    for (int k2 = 0; k2 < 16; k2++){
        unsigned long long b0,b1,b2,b3,c0,c1,c2,c3;
        uint32_t ba = bbase + (uint32_t)k2*2048u;
        asm volatile("ld.shared.v2.b64 {%0,%1}, [%2];" : "=l"(b0),"=l"(b1) : "r"(ba));
        asm volatile("ld.shared.v2.b64 {%0,%1}, [%2];" : "=l"(b2),"=l"(b3) : "r"(ba+512u));
        asm volatile("ld.shared.v2.b64 {%0,%1}, [%2];" : "=l"(c0),"=l"(c1) : "r"(ba+1024u));
        asm volatile("ld.shared.v2.b64 {%0,%1}, [%2];" : "=l"(c2),"=l"(c3) : "r"(ba+1536u));
        #pragma unroll
        for (int i=0;i<8;i++){
            uint32_t aa = abase + (uint32_t)i*AROW + (uint32_t)k2*16u;
            unsigned long long s0,s1;
            asm volatile("ld.shared.b64 %0, [%1];" : "=l"(s0) : "r"(aa));
            asm volatile("ld.shared.b64 %0, [%1];" : "=l"(s1) : "r"(aa+8u));
            asm volatile("fma.rn.f32x2 %0, %1, %2, %0;" : "+l"(acc[i][0]) : "l"(s0), "l"(b0));
            asm volatile("fma.rn.f32x2 %0, %1, %2, %0;" : "+l"(acc[i][1]) : "l"(s0), "l"(b1));
            asm volatile("fma.rn.f32x2 %0, %1, %2, %0;" : "+l"(acc[i][2]) : "l"(s0), "l"(b2));
            asm volatile("fma.rn.f32x2 %0, %1, %2, %0;" : "+l"(acc[i][3]) : "l"(s0), "l"(b3));
            asm volatile("fma.rn.f32x2 %0, %1, %2, %0;" : "+l"(acc[i][0]) : "l"(s1), "l"(c0));
            asm volatile("fma.rn.f32x2 %0, %1, %2, %0;" : "+l"(acc[i][1]) : "l"(s1), "l"(c1));
            asm volatile("fma.rn.f32x2 %0, %1, %2, %0;" : "+l"(acc[i][2]) : "l"(s1), "l"(c2));
            asm volatile("fma.rn.f32x2 %0, %1, %2, %0;" : "+l"(acc[i][3]) : "l"(s1), "l"(c3));
        }
    }
}

// ---------- mlp chunk: plain-A with splats ----------
__device__ __forceinline__ void chunk_splat(unsigned long long (&acc)[8][4], uint32_t abase, uint32_t bbase){
    #pragma unroll 4
    for (int k2 = 0; k2 < 16; k2++){
        unsigned long long b0,b1,b2,b3,c0,c1,c2,c3;
        uint32_t ba = bbase + (uint32_t)k2*2048u;
        asm volatile("ld.shared.v2.b64 {%0,%1}, [%2];" : "=l"(b0),"=l"(b1) : "r"(ba));
        asm volatile("ld.shared.v2.b64 {%0,%1}, [%2];" : "=l"(b2),"=l"(b3) : "r"(ba+512u));
        asm volatile("ld.shared.v2.b64 {%0,%1}, [%2];" : "=l"(c0),"=l"(c1) : "r"(ba+1024u));
        asm volatile("ld.shared.v2.b64 {%0,%1}, [%2];" : "=l"(c2),"=l"(c3) : "r"(ba+1536u));
        #pragma unroll
        for (int i=0;i<8;i++){
            unsigned long long ap; float alo,ahi;
            asm volatile("ld.shared.b64 %0, [%1];" : "=l"(ap) : "r"(abase + (uint32_t)(i*MLP_AS + k2*2)*4u));
            UNPK(alo,ahi,ap);
            unsigned long long s0,s1;
            asm volatile("mov.b64 %0, {%1,%1};" : "=l"(s0) : "f"(alo));
            asm volatile("mov.b64 %0, {%1,%1};" : "=l"(s1) : "f"(ahi));
            asm volatile("fma.rn.f32x2 %0, %1, %2, %0;" : "+l"(acc[i][0]) : "l"(s0), "l"(b0));
            asm volatile("fma.rn.f32x2 %0, %1, %2, %0;" : "+l"(acc[i][1]) : "l"(s0), "l"(b1));
            asm volatile("fma.rn.f32x2 %0, %1, %2, %0;" : "+l"(acc[i][2]) : "l"(s0), "l"(b2));
            asm volatile("fma.rn.f32x2 %0, %1, %2, %0;" : "+l"(acc[i][3]) : "l"(s0), "l"(b3));
            asm volatile("fma.rn.f32x2 %0, %1, %2, %0;" : "+l"(acc[i][0]) : "l"(s1), "l"(c0));
            asm volatile("fma.rn.f32x2 %0, %1, %2, %0;" : "+l"(acc[i][1]) : "l"(s1), "l"(c1));
            asm volatile("fma.rn.f32x2 %0, %1, %2, %0;" : "+l"(acc[i][2]) : "l"(s1), "l"(c2));
            asm volatile("fma.rn.f32x2 %0, %1, %2, %0;" : "+l"(acc[i][3]) : "l"(s1), "l"(c3));
        }
    }
}

// ---------- main fused kernel ----------
__global__ void __launch_bounds__(512,1)
ctx_main(const float* __restrict__ feats, const int* __restrict__ neigh,
         const float* __restrict__ Wm,
         const float* __restrict__ bm, const float* __restrict__ W0,
         const float* __restrict__ b0, const float* __restrict__ W1,
         const float* __restrict__ b1, const float* __restrict__ W2,
         const float* __restrict__ b2, float* __restrict__ out)
{
    extern __shared__ char smem[];
    const uint32_t sb = smem_u32(smem);
    const int tid = threadIdx.x;
    const int tn = tid & 31, tm = tid >> 5;
    const int tile0 = blockIdx.x * 128;
    const int nact = g_nact;
    const int ctxS = 4*nact;
    const int S = ctxS + 24;

    const int gm = tid >> 2, gq = tid & 3;
    const int gp = tile0 + gm;

    unsigned long long acc[8][4];
    #pragma unroll
    for (int i=0;i<8;i++){ acc[i][0]=0ull; acc[i][1]=0ull; acc[i][2]=0ull; acc[i][3]=0ull; }

    #define ISSUE(s2) do{ \
        if ((s2) < S){ \
            const float* _src; \
            if ((s2) < ctxS) _src = Wm + (size_t)g_act[(s2)>>2]*32768 + ((s2)&3)*8192; \
            else { int _t = (s2)-ctxS; const float* _W = (_t<8)?W0:(_t<16)?W1:W2; _src = _W + (_t&7)*8192; } \
            uint32_t _dst = sb + RING_OFF + (uint32_t)((s2)&1)*32768u; \
            _Pragma("unroll") \
            for (int _i=0;_i<4;_i++) CP_ASYNC16(_dst + (uint32_t)(tid+_i*512)*16u, _src + (tid+_i*512)*4); \
        } \
        CP_COMMIT(); \
    }while(0)

    ISSUE(0);

    for (int s = 0; s < S; s++){
        __syncthreads();                 // compute of s-1 done: slot (s+1)&1 free, A/X stable
        ISSUE(s+1);

        if (s < ctxS){
            if ((s & 3) == 0){
                // gather A rows for this tap, duplicated {a,a} pairs
                int k = g_act[s>>2];
                int idx = (gp < NPTS) ? __ldg(neigh + (size_t)gp*KK + k) : NPTS;
                uint32_t ad = sb + (uint32_t)gm*AROW + (uint32_t)gq*ACH;
                if (idx < NPTS){
                    const float4* src = (const float4*)(feats + (size_t)idx*128 + gq*32);
                    #pragma unroll
                    for (int i=0;i<8;i++){
                        float4 v = __ldg(src+i);
                        uint32_t a0 = ad + (uint32_t)i*32u;
                        asm volatile("st.shared.v2.b32 [%0], {%1,%1};" :: "r"(a0),      "r"(__float_as_uint(v.x)) : "memory");
                        asm volatile("st.shared.v2.b32 [%0], {%1,%1};" :: "r"(a0+8u),   "r"(__float_as_uint(v.y)) : "memory");
                        asm volatile("st.shared.v2.b32 [%0], {%1,%1};" :: "r"(a0+16u),  "r"(__float_as_uint(v.z)) : "memory");
                        asm volatile("st.shared.v2.b32 [%0], {%1,%1};" :: "r"(a0+24u),  "r"(__float_as_uint(v.w)) : "memory");
                    }
                } else {
                    #pragma unroll
                    for (int i=0;i<8;i++){
                        uint32_t a0 = ad + (uint32_t)i*32u;
                        asm volatile("st.shared.v2.b32 [%0], {%1,%1};" :: "r"(a0),     "r"(0u) : "memory");
                        asm volatile("st.shared.v2.b32 [%0], {%1,%1};" :: "r"(a0+8u),  "r"(0u) : "memory");
                        asm volatile("st.shared.v2.b32 [%0], {%1,%1};" :: "r"(a0+16u), "r"(0u) : "memory");
                        asm volatile("st.shared.v2.b32 [%0], {%1,%1};" :: "r"(a0+24u), "r"(0u) : "memory");
                    }
                }
            }
        } else {
            int t = s - ctxS;
            if ((t & 7) == 0){
                // write X = acc + bias (relu for later layers) into X region (reuses A footprint)
                const float* bias = (t==0) ? bm : (t==8) ? b0 : b1;
                bool relu = (t != 0);
                float bl[4], bh[4];
                #pragma unroll
                for (int j=0;j<4;j++){ bl[j] = __ldg(bias + tn*4 + j); bh[j] = __ldg(bias + 128 + tn*4 + j); }
                #pragma unroll
                for (int i=0;i<8;i++){
                    int m = tm*8 + i;
                    float f0,f1,f2,f3;
                    UNPK(f0,f1,acc[i][0]); UNPK(f2,f3,acc[i][1]);
                    f0+=bl[0]; f1+=bl[1]; f2+=bl[2]; f3+=bl[3];
                    if (relu){ f0=fmaxf(f0,0.f); f1=fmaxf(f1,0.f); f2=fmaxf(f2,0.f); f3=fmaxf(f3,0.f); }
                    uint32_t xa = sb + (uint32_t)(m*MLP_AS + tn*4)*4u;
                    asm volatile("st.shared.v4.b32 [%0], {%1,%2,%3,%4};" :: "r"(xa),
                        "r"(__float_as_uint(f0)),"r"(__float_as_uint(f1)),
                        "r"(__float_as_uint(f2)),"r"(__float_as_uint(f3)) : "memory");
                    UNPK(f0,f1,acc[i][2]); UNPK(f2,f3,acc[i][3]);
                    f0+=bh[0]; f1+=bh[1]; f2+=bh[2]; f3+=bh[3];
                    if (relu){ f0=fmaxf(f0,0.f); f1=fmaxf(f1,0.f); f2=fmaxf(f2,0.f); f3=fmaxf(f3,0.f); }
                    asm volatile("st.shared.v4.b32 [%0], {%1,%2,%3,%4};" :: "r"(xa + 512u),
                        "r"(__float_as_uint(f0)),"r"(__float_as_uint(f1)),
                        "r"(__float_as_uint(f2)),"r"(__float_as_uint(f3)) : "memory");
                }
                #pragma unroll
                for (int i=0;i<8;i++){ acc[i][0]=0ull; acc[i][1]=0ull; acc[i][2]=0ull; acc[i][3]=0ull; }
            }
        }

        CP_WAIT1();
        __syncthreads();

        uint32_t bbase = sb + RING_OFF + (uint32_t)(s&1)*32768u + (uint32_t)tn*16u;
        if (s < ctxS)
            chunk_dup(acc, sb + (uint32_t)(tm*8)*AROW + (uint32_t)(s&3)*ACH, bbase);
        else
            chunk_splat(acc, sb + (uint32_t)(tm*8*MLP_AS + ((s-ctxS)&7)*32)*4u, bbase);
    }

    // ---- final epilogue: + b2; loc = cols<128, scale = |cols>=128| ----
    float bl[4], bh[4];
    #pragma unroll
    for (int j=0;j<4;j++){ bl[j] = __ldg(b2 + tn*4 + j); bh[j] = __ldg(b2 + 128 + tn*4 + j); }
    #pragma unroll
    for (int i=0;i<8;i++){
        int p = tile0 + tm*8 + i;
        if (p < NPTS){
            float f0,f1,f2,f3;
            UNPK(f0,f1,acc[i][0]); UNPK(f2,f3,acc[i][1]);
            float4 v0 = make_float4(f0+bl[0], f1+bl[1], f2+bl[2], f3+bl[3]);
            *(float4*)(out + (size_t)p*128 + tn*4) = v0;
            UNPK(f0,f1,acc[i][2]); UNPK(f2,f3,acc[i][3]);
            float4 v1 = make_float4(fabsf(f0+bh[0]), fabsf(f1+bh[1]), fabsf(f2+bh[2]), fabsf(f3+bh[3]));
            *(float4*)(out + (size_t)NPTS*128 + (size_t)p*128 + tn*4) = v1;
        }
    }
    #undef ISSUE
}

extern "C" void kernel_launch(void* const* d_in, const int* in_sizes, int n_in,
                              void* d_out, int out_size)
{
    const float* feats = (const float*)d_in[0];
    const int*   neigh = (const int*)d_in[1];
    const float* Wm    = (const float*)d_in[2];
    const float* bm    = (const float*)d_in[3];
    const float* W0    = (const float*)d_in[4];
    const float* b0    = (const float*)d_in[5];
    const float* W1    = (const float*)d_in[6];
    const float* b1    = (const float*)d_in[7];
    const float* W2    = (const float*)d_in[8];
    const float* b2    = (const float*)d_in[9];
    float* out = (float*)d_out;

    static bool cfg = false;
    if (!cfg){
        cudaFuncSetAttribute(ctx_main, cudaFuncAttributeMaxDynamicSharedMemorySize, SMEM_BYTES);
        cfg = true;
    }

    prep_flag_compact<<<KK, 256>>>(Wm);
    ctx_main<<<NTILES, 512, SMEM_BYTES>>>(feats, neigh, Wm, bm, W0, b0, W1, b1, W2, b2, out);
}

// round 10
// speedup vs baseline: 1.2343x; 1.2343x over previous
#include <cuda_runtime.h>
#include <cstdint>

#define NPTS   200000
#define KK     125
#define TILE   64
#define NTILES 3125

#define AS     528u            // A row pitch (bytes): 128 floats + pad
#define XS     1040u           // X row pitch (bytes): 256 floats + pad
#define RING_OFF 66560u        // after X region (64*1040); A (64*528) overlays X start
#define SMEM_BYTES (66560 + 2*16384)

// ---------- PTX helpers ----------
__device__ __forceinline__ uint32_t smem_u32(const void* p){
    uint32_t a; asm("{ .reg .u64 t; cvta.to.shared.u64 t, %1; cvt.u32.u64 %0, t; }":"=r"(a):"l"(p)); return a;
}
#define CP_ASYNC16(dst,src) asm volatile("cp.async.cg.shared.global [%0], [%1], 16;"::"r"(dst),"l"(src):"memory")
#define CP_COMMIT() asm volatile("cp.async.commit_group;":::"memory")
#define CP_WAIT1()  asm volatile("cp.async.wait_group 1;":::"memory")
#define UNPK(lo,hi,p) asm volatile("mov.b64 {%0,%1}, %2;" : "=f"(lo),"=f"(hi) : "l"(p))

// ---------- device scratch ----------
__device__ int g_kflag[KK];
__device__ int g_act[KK];
__device__ int g_nact;
__device__ unsigned int g_done;

// ---------- prep: detect active taps (device-side) ----------
__global__ void prep_flag_compact(const float* __restrict__ Wm){
    int k = blockIdx.x, t = threadIdx.x, any = 0;
    const float* w = Wm + (size_t)k*32768;
    for (int i=t;i<32768;i+=256) any |= (w[i]!=0.f);
    any = __syncthreads_or(any);
    __shared__ unsigned int slast;
    if (t == 0){
        g_kflag[k] = any;
        __threadfence();
        slast = atomicAdd(&g_done, 1u);
    }
    __syncthreads();
    if (slast == KK-1 && t == 0){
        int c = 0;
        for (int kk=0; kk<KK; kk++){
            int fl = *((volatile int*)&g_kflag[kk]);
            if (fl) g_act[c++] = kk;
        }
        g_nact = c;
        g_done = 0;
        __threadfence();
    }
}

// ---------- 16-k chunk GEMM: acc[8 rows][4 n-pairs] += A(8m x 16k) * B(16k x 256n slice) ----------
// AP = A row pitch (bytes). abase -> (row tm*8, chunk k base). bbase -> slot + tn*16.
template<uint32_t AP>
__device__ __forceinline__ void chunk_mma(unsigned long long (&acc)[8][4], uint32_t abase, uint32_t bbase){
    #pragma unroll
    for (int k2 = 0; k2 < 8; k2++){
        unsigned long long b0,b1,b2,b3,c0,c1,c2,c3;
        uint32_t ba = bbase + (uint32_t)k2*2048u;
        asm volatile("ld.shared.v2.b64 {%0,%1}, [%2];" : "=l"(b0),"=l"(b1) : "r"(ba));
        asm volatile("ld.shared.v2.b64 {%0,%1}, [%2];" : "=l"(b2),"=l"(b3) : "r"(ba+512u));
        asm volatile("ld.shared.v2.b64 {%0,%1}, [%2];" : "=l"(c0),"=l"(c1) : "r"(ba+1024u));
        asm volatile("ld.shared.v2.b64 {%0,%1}, [%2];" : "=l"(c2),"=l"(c3) : "r"(ba+1536u));
        #pragma unroll
        for (int i=0;i<8;i++){
            unsigned long long ap; float alo,ahi;
            asm volatile("ld.shared.b64 %0, [%1];" : "=l"(ap) : "r"(abase + (uint32_t)i*AP + (uint32_t)k2*8u));
            UNPK(alo,ahi,ap);
            unsigned long long s0,s1;
            asm volatile("mov.b64 %0, {%1,%1};" : "=l"(s0) : "f"(alo));
            asm volatile("mov.b64 %0, {%1,%1};" : "=l"(s1) : "f"(ahi));
            asm volatile("fma.rn.f32x2 %0, %1, %2, %0;" : "+l"(acc[i][0]) : "l"(s0), "l"(b0));
            asm volatile("fma.rn.f32x2 %0, %1, %2, %0;" : "+l"(acc[i][1]) : "l"(s0), "l"(b1));
            asm volatile("fma.rn.f32x2 %0, %1, %2, %0;" : "+l"(acc[i][2]) : "l"(s0), "l"(b2));
            asm volatile("fma.rn.f32x2 %0, %1, %2, %0;" : "+l"(acc[i][3]) : "l"(s0), "l"(b3));
            asm volatile("fma.rn.f32x2 %0, %1, %2, %0;" : "+l"(acc[i][0]) : "l"(s1), "l"(c0));
            asm volatile("fma.rn.f32x2 %0, %1, %2, %0;" : "+l"(acc[i][1]) : "l"(s1), "l"(c1));
            asm volatile("fma.rn.f32x2 %0, %1, %2, %0;" : "+l"(acc[i][2]) : "l"(s1), "l"(c2));
            asm volatile("fma.rn.f32x2 %0, %1, %2, %0;" : "+l"(acc[i][3]) : "l"(s1), "l"(c3));
        }
    }
}

// ---------- main fused kernel: 64-pt tiles, 256 threads, 2 CTAs/SM ----------
__global__ void __launch_bounds__(256,2)
ctx_main(const float* __restrict__ feats, const int* __restrict__ neigh,
         const float* __restrict__ Wm,
         const float* __restrict__ bm, const float* __restrict__ W0,
         const float* __restrict__ b0, const float* __restrict__ W1,
         const float* __restrict__ b1, const float* __restrict__ W2,
         const float* __restrict__ b2, float* __restrict__ out)
{
    extern __shared__ char smem[];
    const uint32_t sb = smem_u32(smem);
    const int tid = threadIdx.x;
    const int tn = tid & 31, tm = tid >> 5;     // rows tm*8..+7 (tm<8), cols {tn*4..+3, 128+tn*4..+3}
    const int tile0 = blockIdx.x * TILE;
    const int nact = g_nact;
    const int ctxS = 8*nact;                     // 8 chunks (16 k each) per tap
    const int S = ctxS + 48;                     // + 3 layers x 16 chunks

    const int gr = tid >> 2, gq = tid & 3;       // gather: row gr (0..63), quarter gq
    const int gp = tile0 + gr;                   // always < NPTS (exact tiling)

    unsigned long long acc[8][4];
    #pragma unroll
    for (int i=0;i<8;i++){ acc[i][0]=0ull; acc[i][1]=0ull; acc[i][2]=0ull; acc[i][3]=0ull; }

    // B chunk s2 (16 k-rows x 256 cols = 16KB) -> ring slot s2&1
    #define ISSUE(s2) do{ \
        int _s2 = (s2); \
        if (_s2 < S){ \
            const float* _src; \
            if (_s2 < ctxS) _src = Wm + (size_t)g_act[_s2>>3]*32768 + (_s2&7)*4096; \
            else { int _t = _s2-ctxS; const float* _W = (_t<16)?W0:(_t<32)?W1:W2; _src = _W + (_t&15)*4096; } \
            uint32_t _dst = sb + RING_OFF + (uint32_t)(_s2&1)*16384u; \
            _Pragma("unroll") \
            for (int _i=0;_i<4;_i++) CP_ASYNC16(_dst + (uint32_t)(tid+_i*256)*16u, _src + (tid+_i*256)*4); \
        } \
        CP_COMMIT(); \
    }while(0)

    ISSUE(0);

    for (int s = 0; s < S; s++){
        __syncthreads();               // compute s-1 done: slot (s+1)&1 free; A/X stable
        ISSUE(s+1);

        if (s < ctxS){
            if ((s & 7) == 0){
                // synchronous gather of this tap's A rows (LDG float4 + STS v4)
                int k = g_act[s>>3];
                int idx = __ldg(neigh + (size_t)gp*KK + k);
                uint32_t ad = sb + (uint32_t)gr*AS + (uint32_t)gq*128u;
                if (idx < NPTS){
                    const float4* src = (const float4*)(feats + (size_t)idx*128 + gq*32);
                    #pragma unroll
                    for (int i=0;i<8;i++){
                        float4 v = __ldg(src+i);
                        asm volatile("st.shared.v4.b32 [%0], {%1,%2,%3,%4};" :: "r"(ad + (uint32_t)i*16u),
                            "r"(__float_as_uint(v.x)),"r"(__float_as_uint(v.y)),
                            "r"(__float_as_uint(v.z)),"r"(__float_as_uint(v.w)) : "memory");
                    }
                } else {
                    #pragma unroll
                    for (int i=0;i<8;i++)
                        asm volatile("st.shared.v4.b32 [%0], {%1,%1,%1,%1};" :: "r"(ad + (uint32_t)i*16u), "r"(0u) : "memory");
                }
            }
        } else {
            int t = s - ctxS;
            if ((t & 15) == 0){
                // X = acc + bias (relu for later layers); X overlays A (ctx phase over)
                const float* bias = (t==0) ? bm : (t==16) ? b0 : b1;
                bool relu = (t != 0);
                float bl[4], bh[4];
                #pragma unroll
                for (int j=0;j<4;j++){ bl[j] = __ldg(bias + tn*4 + j); bh[j] = __ldg(bias + 128 + tn*4 + j); }
                #pragma unroll
                for (int i=0;i<8;i++){
                    int m = tm*8 + i;
                    float f0,f1,f2,f3;
                    UNPK(f0,f1,acc[i][0]); UNPK(f2,f3,acc[i][1]);
                    f0+=bl[0]; f1+=bl[1]; f2+=bl[2]; f3+=bl[3];
                    if (relu){ f0=fmaxf(f0,0.f); f1=fmaxf(f1,0.f); f2=fmaxf(f2,0.f); f3=fmaxf(f3,0.f); }
                    uint32_t xa = sb + (uint32_t)m*XS + (uint32_t)tn*16u;
                    asm volatile("st.shared.v4.b32 [%0], {%1,%2,%3,%4};" :: "r"(xa),
                        "r"(__float_as_uint(f0)),"r"(__float_as_uint(f1)),
                        "r"(__float_as_uint(f2)),"r"(__float_as_uint(f3)) : "memory");
                    UNPK(f0,f1,acc[i][2]); UNPK(f2,f3,acc[i][3]);
                    f0+=bh[0]; f1+=bh[1]; f2+=bh[2]; f3+=bh[3];
                    if (relu){ f0=fmaxf(f0,0.f); f1=fmaxf(f1,0.f); f2=fmaxf(f2,0.f); f3=fmaxf(f3,0.f); }
                    asm volatile("st.shared.v4.b32 [%0], {%1,%2,%3,%4};" :: "r"(xa + 512u),
                        "r"(__float_as_uint(f0)),"r"(__float_as_uint(f1)),
                        "r"(__float_as_uint(f2)),"r"(__float_as_uint(f3)) : "memory");
                }
                #pragma unroll
                for (int i=0;i<8;i++){ acc[i][0]=0ull; acc[i][1]=0ull; acc[i][2]=0ull; acc[i][3]=0ull; }
            }
        }

        CP_WAIT1();
        __syncthreads();

        uint32_t bbase = sb + RING_OFF + (uint32_t)(s&1)*16384u + (uint32_t)tn*16u;
        if (s < ctxS)
            chunk_mma<AS>(acc, sb + (uint32_t)(tm*8)*AS + (uint32_t)(s&7)*64u, bbase);
        else
            chunk_mma<XS>(acc, sb + (uint32_t)(tm*8)*XS + (uint32_t)((s-ctxS)&15)*64u, bbase);
    }

    // ---- final epilogue: + b2; loc = cols<128, scale = |cols>=128| ----
    float bl[4], bh[4];
    #pragma unroll
    for (int j=0;j<4;j++){ bl[j] = __ldg(b2 + tn*4 + j); bh[j] = __ldg(b2 + 128 + tn*4 + j); }
    #pragma unroll
    for (int i=0;i<8;i++){
        int p = tile0 + tm*8 + i;
        float f0,f1,f2,f3;
        UNPK(f0,f1,acc[i][0]); UNPK(f2,f3,acc[i][1]);
        float4 v0 = make_float4(f0+bl[0], f1+bl[1], f2+bl[2], f3+bl[3]);
        *(float4*)(out + (size_t)p*128 + tn*4) = v0;
        UNPK(f0,f1,acc[i][2]); UNPK(f2,f3,acc[i][3]);
        float4 v1 = make_float4(fabsf(f0+bh[0]), fabsf(f1+bh[1]), fabsf(f2+bh[2]), fabsf(f3+bh[3]));
        *(float4*)(out + (size_t)NPTS*128 + (size_t)p*128 + tn*4) = v1;
    }
    #undef ISSUE
}

extern "C" void kernel_launch(void* const* d_in, const int* in_sizes, int n_in,
                              void* d_out, int out_size)
{
    const float* feats = (const float*)d_in[0];
    const int*   neigh = (const int*)d_in[1];
    const float* Wm    = (const float*)d_in[2];
    const float* bm    = (const float*)d_in[3];
    const float* W0    = (const float*)d_in[4];
    const float* b0    = (const float*)d_in[5];
    const float* W1    = (const float*)d_in[6];
    const float* b1    = (const float*)d_in[7];
    const float* W2    = (const float*)d_in[8];
    const float* b2    = (const float*)d_in[9];
    float* out = (float*)d_out;

    static bool cfg = false;
    if (!cfg){
        cudaFuncSetAttribute(ctx_main, cudaFuncAttributeMaxDynamicSharedMemorySize, SMEM_BYTES);
        cfg = true;
    }

    prep_flag_compact<<<KK, 256>>>(Wm);
    ctx_main<<<NTILES, 256, SMEM_BYTES>>>(feats, neigh, Wm, bm, W0, b0, W1, b1, W2, b2, out);
}